// round 15
// baseline (speedup 1.0000x reference)
#include <cuda_runtime.h>
#include <cuda_fp16.h>
#include <math.h>
#include <stdint.h>

#define BATCH 16
#define C3C 512
#define C4C 1024
#define CIN 1536
#define COUT 512
#define HH 64
#define WW 64
#define HW 4096
#define H4 32
#define NROI 10

#define TM 128
#define TN 256
#define BK 64
#define KIT (CIN / BK)          // 24
#define AST 72                  // A smem stride (halves): 36 words -> conflict-free ldmatrix
#define BST 264                 // B smem stride (halves): 132 words -> conflict-free ldmatrix.trans
#define A_BYTES (TM * AST * 2)  // 18432
#define B_BYTES (BK * BST * 2)  // 33792
#define STAGE_BYTES (A_BYTES + B_BYTES)  // 52224
#define NSTAGES 3
#define SMEM_TOTAL (NSTAGES * STAGE_BYTES + 16)   // 156688

// Scratch (static device arrays — allocation-guard safe)
__device__ __half g_wh[(size_t)COUT * CIN];           // W -> fp16
__device__ __half g_c3h[(size_t)BATCH * C3C * HW];    // c3 -> fp16
__device__ __half g_c4uh[(size_t)BATCH * C4C * HW];   // upsampled c4 -> fp16
__device__ __half g_attrh[(size_t)BATCH * COUT * HW]; // conv+bn+relu output (fp16)

__device__ __forceinline__ uint32_t cvta_smem(const void* p) {
    uint32_t a;
    asm("{ .reg .u64 t; cvta.to.shared.u64 t, %1; cvt.u32.u64 %0, t; }" : "=r"(a) : "l"(p));
    return a;
}
__device__ __forceinline__ void cpasync16(uint32_t dst, const void* src) {
    asm volatile("cp.async.cg.shared.global [%0], [%1], 16;" :: "r"(dst), "l"(src) : "memory");
}
__device__ __forceinline__ void cp_commit() {
    asm volatile("cp.async.commit_group;" ::: "memory");
}
__device__ __forceinline__ void ldsm4(uint32_t addr, unsigned& r0, unsigned& r1,
                                      unsigned& r2, unsigned& r3) {
    asm volatile("ldmatrix.sync.aligned.m8n8.x4.shared.b16 {%0,%1,%2,%3}, [%4];"
                 : "=r"(r0), "=r"(r1), "=r"(r2), "=r"(r3) : "r"(addr));
}
__device__ __forceinline__ void ldsm4t(uint32_t addr, unsigned& r0, unsigned& r1,
                                       unsigned& r2, unsigned& r3) {
    asm volatile("ldmatrix.sync.aligned.m8n8.x4.trans.shared.b16 {%0,%1,%2,%3}, [%4];"
                 : "=r"(r0), "=r"(r1), "=r"(r2), "=r"(r3) : "r"(addr));
}

// ---------------------------------------------------------------------------
// Prep kernels
// ---------------------------------------------------------------------------
__global__ void __launch_bounds__(256) prep_w_kernel(const float* __restrict__ Wc) {
    int i = blockIdx.x * blockDim.x + threadIdx.x;
    g_wh[i] = __float2half_rn(Wc[i]);
}

__global__ void __launch_bounds__(256) prep_c3_kernel(const float* __restrict__ c3) {
    size_t i = (size_t)blockIdx.x * blockDim.x + threadIdx.x;
    float4 v = *(const float4*)(c3 + i * 4);
    __half2* o = (__half2*)(g_c3h + i * 4);
    o[0] = __floats2half2_rn(v.x, v.y);
    o[1] = __floats2half2_rn(v.z, v.w);
}

__global__ void __launch_bounds__(256) upsample_kernel(const float* __restrict__ c4) {
    size_t idx = (size_t)blockIdx.x * blockDim.x + threadIdx.x;
    int w = (int)(idx & 63);
    int h = (int)((idx >> 6) & 63);
    size_t bc = idx >> 12;
    const float* __restrict__ src = c4 + bc * (H4 * H4);

    float fy = h * 0.5f - 0.25f;
    int h0 = (int)floorf(fy);
    float ty = fy - (float)h0;
    int h1 = min(h0 + 1, H4 - 1);
    h0 = max(h0, 0);

    float fx = w * 0.5f - 0.25f;
    int w0 = (int)floorf(fx);
    float tx = fx - (float)w0;
    int w1 = min(w0 + 1, H4 - 1);
    w0 = max(w0, 0);

    float v00 = src[h0 * H4 + w0];
    float v01 = src[h0 * H4 + w1];
    float v10 = src[h1 * H4 + w0];
    float v11 = src[h1 * H4 + w1];
    float v = (1.f - ty) * ((1.f - tx) * v00 + tx * v01)
            +        ty  * ((1.f - tx) * v10 + tx * v11);
    g_c4uh[idx] = __float2half_rn(v);
}

// ---------------------------------------------------------------------------
// GEMM: fp16 mma.sync m16n8k16, CTA 128x256xBK64, warp tile 64x64,
// 3-stage cp.async pipeline, ldmatrix fragment loads. 1 CTA/SM.
// ---------------------------------------------------------------------------
__global__ void __launch_bounds__(256, 1) gemm_kernel(
    const float* __restrict__ bconv, const float* __restrict__ gamma,
    const float* __restrict__ beta, const float* __restrict__ mean,
    const float* __restrict__ var)
{
    extern __shared__ __align__(16) char dsm[];
    const uint32_t smem0 = cvta_smem(dsm);

    const int tid = threadIdx.x;
    const int lane = tid & 31;
    const int warpId = tid >> 5;
    const int warpM = warpId & 1;    // 2 groups of 64 rows
    const int warpN = warpId >> 1;   // 4 groups of 64 cols
    const int lane4 = lane & 3;
    const int laneq = lane >> 2;

    const int b = blockIdx.z;
    const int mBase = blockIdx.y * TM;
    const int nBase = blockIdx.x * TN;

    const __half* __restrict__ c3b = g_c3h + (size_t)b * C3C * HW;
    const __half* __restrict__ c4b = g_c4uh + (size_t)b * C4C * HW;

    // cp.async chunk mapping:
    // A: 128 rows x 8 chunks(16B) = 1024 chunks -> 4/thread
    // B: 64 rows x 32 chunks = 2048 chunks -> 8/thread
    auto issue_stage = [&](int i) {
        const int k0 = i * BK;
        const uint32_t sA = smem0 + (uint32_t)((i % NSTAGES) * STAGE_BYTES);
        const uint32_t sB = sA + (uint32_t)A_BYTES;
#pragma unroll
        for (int j = 0; j < 4; j++) {
            int chunk = tid + 256 * j;
            int m = chunk >> 3, cA = chunk & 7;
            cpasync16(sA + (uint32_t)(m * (AST * 2) + cA * 16),
                      g_wh + (size_t)(mBase + m) * CIN + k0 + cA * 8);
        }
#pragma unroll
        for (int j = 0; j < 8; j++) {
            int chunk = tid + 256 * j;
            int k = chunk >> 5, cB = chunk & 31;
            int ch = k0 + k;
            const __half* srow = (ch < C3C) ? (c3b + (size_t)ch * HW)
                                            : (c4b + (size_t)(ch - C3C) * HW);
            cpasync16(sB + (uint32_t)(k * (BST * 2) + cB * 16),
                      srow + nBase + cB * 8);
        }
        cp_commit();
    };

    // ldmatrix per-thread offsets (bytes)
    const uint32_t offA = (uint32_t)(((warpM * 64 + (lane & 15)) * AST + (lane >> 4) * 8) * 2);
    const uint32_t offB = (uint32_t)(((lane & 15) * BST + warpN * 64 + (lane >> 4) * 8) * 2);

    float acc[4][8][4];
#pragma unroll
    for (int i = 0; i < 4; i++)
#pragma unroll
        for (int j = 0; j < 8; j++)
#pragma unroll
            for (int r = 0; r < 4; r++) acc[i][j][r] = 0.f;

    issue_stage(0);
    issue_stage(1);

    for (int i = 0; i < KIT; i++) {
        if (i + 2 < KIT) {
            asm volatile("cp.async.wait_group 1;" ::: "memory");
        } else {
            asm volatile("cp.async.wait_group 0;" ::: "memory");
        }
        __syncthreads();
        if (i + 2 < KIT) issue_stage(i + 2);

        const uint32_t As = smem0 + (uint32_t)((i % NSTAGES) * STAGE_BYTES);
        const uint32_t Bs = As + (uint32_t)A_BYTES;

#pragma unroll
        for (int ks = 0; ks < BK; ks += 16) {
            unsigned af[4][4];
#pragma unroll
            for (int ii = 0; ii < 4; ii++)
                ldsm4(As + offA + (uint32_t)(ii * 16 * AST * 2 + ks * 2),
                      af[ii][0], af[ii][1], af[ii][2], af[ii][3]);
            unsigned bf[8][2];
#pragma unroll
            for (int J = 0; J < 4; J++) {
                unsigned r0, r1, r2, r3;
                ldsm4t(Bs + offB + (uint32_t)(ks * BST * 2 + J * 32), r0, r1, r2, r3);
                bf[2 * J][0] = r0; bf[2 * J][1] = r1;
                bf[2 * J + 1][0] = r2; bf[2 * J + 1][1] = r3;
            }
#pragma unroll
            for (int ii = 0; ii < 4; ii++)
#pragma unroll
                for (int jj = 0; jj < 8; jj++) {
                    asm volatile(
                        "mma.sync.aligned.m16n8k16.row.col.f32.f16.f16.f32 "
                        "{%0,%1,%2,%3}, {%4,%5,%6,%7}, {%8,%9}, {%0,%1,%2,%3};\n"
                        : "+f"(acc[ii][jj][0]), "+f"(acc[ii][jj][1]),
                          "+f"(acc[ii][jj][2]), "+f"(acc[ii][jj][3])
                        : "r"(af[ii][0]), "r"(af[ii][1]), "r"(af[ii][2]), "r"(af[ii][3]),
                          "r"(bf[jj][0]), "r"(bf[jj][1]));
                }
        }
        __syncthreads();
    }

    // epilogue: bias + BN + ReLU -> g_attrh (fp16)
#pragma unroll
    for (int i = 0; i < 4; i++) {
        int r0 = mBase + warpM * 64 + i * 16 + laneq;
        int r1 = r0 + 8;
        float inv0 = gamma[r0] * rsqrtf(var[r0] + 1e-5f);
        float sh0 = beta[r0] + (bconv[r0] - mean[r0]) * inv0;
        float inv1 = gamma[r1] * rsqrtf(var[r1] + 1e-5f);
        float sh1 = beta[r1] + (bconv[r1] - mean[r1]) * inv1;
        __half* base0 = g_attrh + ((size_t)b * COUT + r0) * HW + nBase;
        __half* base1 = g_attrh + ((size_t)b * COUT + r1) * HW + nBase;
#pragma unroll
        for (int j = 0; j < 8; j++) {
            int col = warpN * 64 + j * 8 + 2 * lane4;
            *(__half2*)(base0 + col) = __floats2half2_rn(
                fmaxf(acc[i][j][0] * inv0 + sh0, 0.f),
                fmaxf(acc[i][j][1] * inv0 + sh0, 0.f));
            *(__half2*)(base1 + col) = __floats2half2_rn(
                fmaxf(acc[i][j][2] * inv1 + sh1, 0.f),
                fmaxf(acc[i][j][3] * inv1 + sh1, 0.f));
        }
    }
}

// ---------------------------------------------------------------------------
__global__ void copy_boxes_kernel(const float* __restrict__ boxes, float* __restrict__ out) {
    int i = blockIdx.x * blockDim.x + threadIdx.x;
    if (i < BATCH * NROI * 4) out[i] = boxes[i];
}

// ---------------------------------------------------------------------------
// ROI adaptive-avg-pool 5x5. grid(160,32), block = 16-ch chunk. fp16 input.
// ---------------------------------------------------------------------------
__global__ void __launch_bounds__(256) roi_pool_kernel(const float* __restrict__ boxes,
                                                       float* __restrict__ out)
{
    const int br = blockIdx.x;
    const int chunk = blockIdx.y;
    const int b = br / NROI;
    const float* box = boxes + (size_t)br * 4;

    const float sx = (float)WW / 512.0f;
    const float sy = (float)HH / 512.0f;

    int x1 = min(max((int)floorf(box[0] * sx), 0), WW - 1);
    int y1 = min(max((int)floorf(box[1] * sy), 0), HH - 1);
    int x2 = min(max((int)ceilf(box[2] * sx), 0), WW - 1);
    int y2 = min(max((int)ceilf(box[3] * sy), 0), HH - 1);
    if (x2 <= x1) x2 = min(x1 + 1, WW);
    if (y2 <= y1) y2 = min(y1 + 1, HH);
    const int Lx = x2 - x1;
    const int Ly = y2 - y1;

    const int warp = threadIdx.x >> 5;
    const int lane = threadIdx.x & 31;

    int hs = 0, he = 0, ws = 0, we = 0;
    float invArea = 0.f;
    if (lane < 25) {
        int p = lane / 5, q = lane % 5;
        hs = y1 + (p * Ly) / 5;
        he = y1 + ((p + 1) * Ly + 4) / 5;
        ws = x1 + (q * Lx) / 5;
        we = x1 + ((q + 1) * Lx + 4) / 5;
        invArea = 1.0f / (float)((he - hs) * (we - ws));
    }

    const __half* attrB = g_attrh + (size_t)b * COUT * HW;
    float* outBR = out + (size_t)BATCH * NROI * 4 + (size_t)br * COUT * 25;

    for (int cc = warp; cc < 16; cc += 8) {
        int c = chunk * 16 + cc;
        if (lane < 25) {
            const __half* plane = attrB + (size_t)c * HW;
            float s = 0.f;
            for (int h = hs; h < he; h++) {
                const __half* row = plane + h * WW;
                for (int w = ws; w < we; w++) s += __half2float(__ldg(row + w));
            }
            outBR[(size_t)c * 25 + lane] = s * invArea;
        }
    }
}

// ---------------------------------------------------------------------------
extern "C" void kernel_launch(void* const* d_in, const int* in_sizes, int n_in,
                              void* d_out, int out_size)
{
    const float* c3    = (const float*)d_in[0];
    const float* c4    = (const float*)d_in[1];
    const float* boxes = (const float*)d_in[2];
    const float* wconv = (const float*)d_in[3];
    const float* bconv = (const float*)d_in[4];
    const float* gamma = (const float*)d_in[5];
    const float* beta  = (const float*)d_in[6];
    const float* mean  = (const float*)d_in[7];
    const float* var   = (const float*)d_in[8];
    float* out = (float*)d_out;

    static int configured = 0;
    if (!configured) {
        cudaFuncSetAttribute(gemm_kernel,
                             cudaFuncAttributeMaxDynamicSharedMemorySize, SMEM_TOTAL);
        configured = 1;
    }

    prep_w_kernel<<<COUT * CIN / 256, 256>>>(wconv);
    prep_c3_kernel<<<(size_t)BATCH * C3C * HW / 4 / 256, 256>>>(c3);
    upsample_kernel<<<262144, 256>>>(c4);

    gemm_kernel<<<dim3(HW / TN, COUT / TM, BATCH), 256, SMEM_TOTAL>>>(
        bconv, gamma, beta, mean, var);

    copy_boxes_kernel<<<3, 256>>>(boxes, out);

    roi_pool_kernel<<<dim3(BATCH * NROI, 32), 256>>>(boxes, out);
}

// round 16
// speedup vs baseline: 1.0589x; 1.0589x over previous
#include <cuda_runtime.h>
#include <cuda_fp16.h>
#include <math.h>
#include <stdint.h>

#define BATCH 16
#define C3C 512
#define C4C 1024
#define CIN 1536
#define COUT 512
#define HH 64
#define WW 64
#define HW 4096
#define H4 32
#define NROI 10

#define TM 128
#define TN 128
#define BK 64
#define KIT (CIN / BK)          // 24
#define AST 72                  // A smem stride (halves): 36 words, conflict-free ldmatrix
#define BST 136                 // B smem stride (halves): 68 words, conflict-free ldmatrix.trans
#define A_BYTES (TM * AST * 2)  // 18432
#define B_BYTES (BK * BST * 2)  // 17408
#define STAGE_BYTES (A_BYTES + B_BYTES)  // 35840
#define NSTAGES 3
#define SMEM_TOTAL (NSTAGES * STAGE_BYTES + 16)   // 107536

// Scratch (static device arrays — allocation-guard safe)
__device__ __half g_wh[(size_t)COUT * CIN];           // W -> fp16
__device__ __half g_c3h[(size_t)BATCH * C3C * HW];    // c3 -> fp16
__device__ __half g_c4uh[(size_t)BATCH * C4C * HW];   // upsampled c4 -> fp16
__device__ __half g_attrh[(size_t)BATCH * COUT * HW]; // conv+bn+relu output (fp16)

__device__ __forceinline__ uint32_t cvta_smem(const void* p) {
    uint32_t a;
    asm("{ .reg .u64 t; cvta.to.shared.u64 t, %1; cvt.u32.u64 %0, t; }" : "=r"(a) : "l"(p));
    return a;
}
__device__ __forceinline__ void cpasync16(uint32_t dst, const void* src) {
    asm volatile("cp.async.cg.shared.global [%0], [%1], 16;" :: "r"(dst), "l"(src) : "memory");
}
__device__ __forceinline__ void cp_commit() {
    asm volatile("cp.async.commit_group;" ::: "memory");
}
__device__ __forceinline__ void ldsm4(uint32_t addr, unsigned& r0, unsigned& r1,
                                      unsigned& r2, unsigned& r3) {
    asm volatile("ldmatrix.sync.aligned.m8n8.x4.shared.b16 {%0,%1,%2,%3}, [%4];"
                 : "=r"(r0), "=r"(r1), "=r"(r2), "=r"(r3) : "r"(addr));
}
__device__ __forceinline__ void ldsm4t(uint32_t addr, unsigned& r0, unsigned& r1,
                                       unsigned& r2, unsigned& r3) {
    asm volatile("ldmatrix.sync.aligned.m8n8.x4.trans.shared.b16 {%0,%1,%2,%3}, [%4];"
                 : "=r"(r0), "=r"(r1), "=r"(r2), "=r"(r3) : "r"(addr));
}

// ---------------------------------------------------------------------------
// Prep kernels
// ---------------------------------------------------------------------------
__global__ void __launch_bounds__(256) prep_w_kernel(const float* __restrict__ Wc) {
    int i = blockIdx.x * blockDim.x + threadIdx.x;
    g_wh[i] = __float2half_rn(Wc[i]);
}

__global__ void __launch_bounds__(256) prep_c3_kernel(const float* __restrict__ c3) {
    size_t i = (size_t)blockIdx.x * blockDim.x + threadIdx.x;
    float4 v = *(const float4*)(c3 + i * 4);
    __half2* o = (__half2*)(g_c3h + i * 4);
    o[0] = __floats2half2_rn(v.x, v.y);
    o[1] = __floats2half2_rn(v.z, v.w);
}

__global__ void __launch_bounds__(256) upsample_kernel(const float* __restrict__ c4) {
    size_t idx = (size_t)blockIdx.x * blockDim.x + threadIdx.x;
    int w = (int)(idx & 63);
    int h = (int)((idx >> 6) & 63);
    size_t bc = idx >> 12;
    const float* __restrict__ src = c4 + bc * (H4 * H4);

    float fy = h * 0.5f - 0.25f;
    int h0 = (int)floorf(fy);
    float ty = fy - (float)h0;
    int h1 = min(h0 + 1, H4 - 1);
    h0 = max(h0, 0);

    float fx = w * 0.5f - 0.25f;
    int w0 = (int)floorf(fx);
    float tx = fx - (float)w0;
    int w1 = min(w0 + 1, H4 - 1);
    w0 = max(w0, 0);

    float v00 = src[h0 * H4 + w0];
    float v01 = src[h0 * H4 + w1];
    float v10 = src[h1 * H4 + w0];
    float v11 = src[h1 * H4 + w1];
    float v = (1.f - ty) * ((1.f - tx) * v00 + tx * v01)
            +        ty  * ((1.f - tx) * v10 + tx * v11);
    g_c4uh[idx] = __float2half_rn(v);
}

// ---------------------------------------------------------------------------
// GEMM: fp16 mma.sync m16n8k16, CTA 128x128xBK64, warp tile 64x32,
// 3-stage cp.async pipeline, ldmatrix fragment loads, 2 CTA/SM.
// ---------------------------------------------------------------------------
__global__ void __launch_bounds__(256, 2) gemm_kernel(
    const float* __restrict__ bconv, const float* __restrict__ gamma,
    const float* __restrict__ beta, const float* __restrict__ mean,
    const float* __restrict__ var)
{
    extern __shared__ __align__(16) char dsm[];
    const uint32_t smem0 = cvta_smem(dsm);

    const int tid = threadIdx.x;
    const int lane = tid & 31;
    const int warpId = tid >> 5;
    const int warpM = warpId & 1;    // 2 groups of 64 rows
    const int warpN = warpId >> 1;   // 4 groups of 32 cols
    const int lane4 = lane & 3;
    const int laneq = lane >> 2;

    const int b = blockIdx.z;
    const int mBase = blockIdx.y * TM;
    const int nBase = blockIdx.x * TN;

    const __half* __restrict__ c3b = g_c3h + (size_t)b * C3C * HW;
    const __half* __restrict__ c4b = g_c4uh + (size_t)b * C4C * HW;

    // cp.async chunk mapping:
    // A: 128 rows x 8 chunks(16B per 64-half row) = 1024 chunks -> 4/thread
    // B: 64 rows x 16 chunks(128-half row) = 1024 chunks -> 4/thread
    auto issue_stage = [&](int i) {
        const int k0 = i * BK;
        const uint32_t sA = smem0 + (uint32_t)((i % NSTAGES) * STAGE_BYTES);
        const uint32_t sB = sA + (uint32_t)A_BYTES;
#pragma unroll
        for (int j = 0; j < 4; j++) {
            int chunk = tid + 256 * j;
            int m = chunk >> 3, cA = chunk & 7;
            cpasync16(sA + (uint32_t)(m * (AST * 2) + cA * 16),
                      g_wh + (size_t)(mBase + m) * CIN + k0 + cA * 8);
        }
#pragma unroll
        for (int j = 0; j < 4; j++) {
            int chunk = tid + 256 * j;
            int k = chunk >> 4, cB = chunk & 15;
            int ch = k0 + k;
            const __half* srow = (ch < C3C) ? (c3b + (size_t)ch * HW)
                                            : (c4b + (size_t)(ch - C3C) * HW);
            cpasync16(sB + (uint32_t)(k * (BST * 2) + cB * 16),
                      srow + nBase + cB * 8);
        }
        cp_commit();
    };

    // ldmatrix per-thread offsets (bytes)
    const uint32_t offA = (uint32_t)(((warpM * 64 + (lane & 15)) * AST + (lane >> 4) * 8) * 2);
    const uint32_t offB = (uint32_t)(((lane & 15) * BST + warpN * 32 + (lane >> 4) * 8) * 2);

    float acc[4][4][4];
#pragma unroll
    for (int i = 0; i < 4; i++)
#pragma unroll
        for (int j = 0; j < 4; j++)
#pragma unroll
            for (int r = 0; r < 4; r++) acc[i][j][r] = 0.f;

    issue_stage(0);
    issue_stage(1);

    for (int i = 0; i < KIT; i++) {
        if (i + 2 < KIT) {
            asm volatile("cp.async.wait_group 1;" ::: "memory");
        } else {
            asm volatile("cp.async.wait_group 0;" ::: "memory");
        }
        __syncthreads();
        if (i + 2 < KIT) issue_stage(i + 2);

        const uint32_t As = smem0 + (uint32_t)((i % NSTAGES) * STAGE_BYTES);
        const uint32_t Bs = As + (uint32_t)A_BYTES;

#pragma unroll
        for (int ks = 0; ks < BK; ks += 16) {
            unsigned af[4][4];
#pragma unroll
            for (int ii = 0; ii < 4; ii++)
                ldsm4(As + offA + (uint32_t)(ii * 16 * AST * 2 + ks * 2),
                      af[ii][0], af[ii][1], af[ii][2], af[ii][3]);
            unsigned bf[4][2];
#pragma unroll
            for (int J = 0; J < 2; J++) {
                unsigned r0, r1, r2, r3;
                ldsm4t(Bs + offB + (uint32_t)(ks * BST * 2 + J * 32), r0, r1, r2, r3);
                bf[2 * J][0] = r0; bf[2 * J][1] = r1;
                bf[2 * J + 1][0] = r2; bf[2 * J + 1][1] = r3;
            }
#pragma unroll
            for (int ii = 0; ii < 4; ii++)
#pragma unroll
                for (int jj = 0; jj < 4; jj++) {
                    asm volatile(
                        "mma.sync.aligned.m16n8k16.row.col.f32.f16.f16.f32 "
                        "{%0,%1,%2,%3}, {%4,%5,%6,%7}, {%8,%9}, {%0,%1,%2,%3};\n"
                        : "+f"(acc[ii][jj][0]), "+f"(acc[ii][jj][1]),
                          "+f"(acc[ii][jj][2]), "+f"(acc[ii][jj][3])
                        : "r"(af[ii][0]), "r"(af[ii][1]), "r"(af[ii][2]), "r"(af[ii][3]),
                          "r"(bf[jj][0]), "r"(bf[jj][1]));
                }
        }
        __syncthreads();
    }

    // epilogue: bias + BN + ReLU -> g_attrh (fp16)
#pragma unroll
    for (int i = 0; i < 4; i++) {
        int r0 = mBase + warpM * 64 + i * 16 + laneq;
        int r1 = r0 + 8;
        float inv0 = gamma[r0] * rsqrtf(var[r0] + 1e-5f);
        float sh0 = beta[r0] + (bconv[r0] - mean[r0]) * inv0;
        float inv1 = gamma[r1] * rsqrtf(var[r1] + 1e-5f);
        float sh1 = beta[r1] + (bconv[r1] - mean[r1]) * inv1;
        __half* base0 = g_attrh + ((size_t)b * COUT + r0) * HW + nBase;
        __half* base1 = g_attrh + ((size_t)b * COUT + r1) * HW + nBase;
#pragma unroll
        for (int j = 0; j < 4; j++) {
            int col = warpN * 32 + j * 8 + 2 * lane4;
            *(__half2*)(base0 + col) = __floats2half2_rn(
                fmaxf(acc[i][j][0] * inv0 + sh0, 0.f),
                fmaxf(acc[i][j][1] * inv0 + sh0, 0.f));
            *(__half2*)(base1 + col) = __floats2half2_rn(
                fmaxf(acc[i][j][2] * inv1 + sh1, 0.f),
                fmaxf(acc[i][j][3] * inv1 + sh1, 0.f));
        }
    }
}

// ---------------------------------------------------------------------------
__global__ void copy_boxes_kernel(const float* __restrict__ boxes, float* __restrict__ out) {
    int i = blockIdx.x * blockDim.x + threadIdx.x;
    if (i < BATCH * NROI * 4) out[i] = boxes[i];
}

// ---------------------------------------------------------------------------
// ROI adaptive-avg-pool 5x5. grid(160,32), block = 16-ch chunk. fp16 input.
// ---------------------------------------------------------------------------
__global__ void __launch_bounds__(256) roi_pool_kernel(const float* __restrict__ boxes,
                                                       float* __restrict__ out)
{
    const int br = blockIdx.x;
    const int chunk = blockIdx.y;
    const int b = br / NROI;
    const float* box = boxes + (size_t)br * 4;

    const float sx = (float)WW / 512.0f;
    const float sy = (float)HH / 512.0f;

    int x1 = min(max((int)floorf(box[0] * sx), 0), WW - 1);
    int y1 = min(max((int)floorf(box[1] * sy), 0), HH - 1);
    int x2 = min(max((int)ceilf(box[2] * sx), 0), WW - 1);
    int y2 = min(max((int)ceilf(box[3] * sy), 0), HH - 1);
    if (x2 <= x1) x2 = min(x1 + 1, WW);
    if (y2 <= y1) y2 = min(y1 + 1, HH);
    const int Lx = x2 - x1;
    const int Ly = y2 - y1;

    const int warp = threadIdx.x >> 5;
    const int lane = threadIdx.x & 31;

    int hs = 0, he = 0, ws = 0, we = 0;
    float invArea = 0.f;
    if (lane < 25) {
        int p = lane / 5, q = lane % 5;
        hs = y1 + (p * Ly) / 5;
        he = y1 + ((p + 1) * Ly + 4) / 5;
        ws = x1 + (q * Lx) / 5;
        we = x1 + ((q + 1) * Lx + 4) / 5;
        invArea = 1.0f / (float)((he - hs) * (we - ws));
    }

    const __half* attrB = g_attrh + (size_t)b * COUT * HW;
    float* outBR = out + (size_t)BATCH * NROI * 4 + (size_t)br * COUT * 25;

    for (int cc = warp; cc < 16; cc += 8) {
        int c = chunk * 16 + cc;
        if (lane < 25) {
            const __half* plane = attrB + (size_t)c * HW;
            float s = 0.f;
            for (int h = hs; h < he; h++) {
                const __half* row = plane + h * WW;
                for (int w = ws; w < we; w++) s += __half2float(__ldg(row + w));
            }
            outBR[(size_t)c * 25 + lane] = s * invArea;
        }
    }
}

// ---------------------------------------------------------------------------
extern "C" void kernel_launch(void* const* d_in, const int* in_sizes, int n_in,
                              void* d_out, int out_size)
{
    const float* c3    = (const float*)d_in[0];
    const float* c4    = (const float*)d_in[1];
    const float* boxes = (const float*)d_in[2];
    const float* wconv = (const float*)d_in[3];
    const float* bconv = (const float*)d_in[4];
    const float* gamma = (const float*)d_in[5];
    const float* beta  = (const float*)d_in[6];
    const float* mean  = (const float*)d_in[7];
    const float* var   = (const float*)d_in[8];
    float* out = (float*)d_out;

    static int configured = 0;
    if (!configured) {
        cudaFuncSetAttribute(gemm_kernel,
                             cudaFuncAttributeMaxDynamicSharedMemorySize, SMEM_TOTAL);
        configured = 1;
    }

    prep_w_kernel<<<COUT * CIN / 256, 256>>>(wconv);
    prep_c3_kernel<<<(size_t)BATCH * C3C * HW / 4 / 256, 256>>>(c3);
    upsample_kernel<<<262144, 256>>>(c4);

    gemm_kernel<<<dim3(HW / TN, COUT / TM, BATCH), 256, SMEM_TOTAL>>>(
        bconv, gamma, beta, mean, var);

    copy_boxes_kernel<<<3, 256>>>(boxes, out);

    roi_pool_kernel<<<dim3(BATCH * NROI, 32), 256>>>(boxes, out);
}